// round 13
// baseline (speedup 1.0000x reference)
#include <cuda_runtime.h>
#include <cuda_bf16.h>
#include <cstdint>
#include <cstddef>

// LSTM_824633721296: 2-layer LSTM (B=1024, T=512, I=8, H=64) + FC (O=10)
// Round-13: merged phases -> 2 syncthreads/step. Phase1 = GEMM0(t)+GEMM1(t-1)
// (mma.sync m16n8k16, bf16 weights register-resident, h hi/lo 2-term) with
// direct gate stores (xg+bias folded by the D-owner, no RMW). Phase2 =
// elem0(t)+elem1(t-1). 512 threads, 1 m-tile/warp. tanh.approx activations.

#define BT       8
#define NB       128
#define NTHREADS 512
#define HID      64
#define TSTEPS   512
#define IDIM     8
#define ODIM     10

#define GSTR 260            // gate buffer stride (floats)
#define W0S  144            // W0 row stride bytes (64 bf16 + pad)
#define W1S  256            // W1 row stride bytes (128 bf16, XOR-swizzled)
#define B0S  144            // B0 row stride bytes
#define B1S  272            // B1 row stride bytes

// smem byte offsets
#define SM_W0H 0            // [256][144] staging
#define SM_W1H 36864        // [256][256] swizzled
#define SM_B0H 102400       // [8][144]  h0 hi
#define SM_B0L 103552       // [8][144]  h0 lo
#define SM_B1H 104704       // [8][272]  [h0new | h1old] hi
#define SM_B1L 106880       // [8][272]  lo
#define SM_G0  109056       // f32 [8][260]
#define SM_G1  117376       // f32 [8][260]
#define SM_XS  125696       // f32 [8][8]
#define SM_H1F 125952       // f32 [8][64]
#define SMEM_BYTES 128000

__device__ __forceinline__ void ldmx4(uint32_t r[4], uint32_t addr) {
    asm volatile("ldmatrix.sync.aligned.m8n8.x4.shared.b16 {%0,%1,%2,%3}, [%4];"
                 : "=r"(r[0]), "=r"(r[1]), "=r"(r[2]), "=r"(r[3]) : "r"(addr));
}
__device__ __forceinline__ void mma16816(float d[4], const uint32_t a[4],
                                         uint32_t b0, uint32_t b1) {
    asm volatile("mma.sync.aligned.m16n8k16.row.col.f32.bf16.bf16.f32 "
                 "{%0,%1,%2,%3}, {%4,%5,%6,%7}, {%8,%9}, {%0,%1,%2,%3};"
                 : "+f"(d[0]), "+f"(d[1]), "+f"(d[2]), "+f"(d[3])
                 : "r"(a[0]), "r"(a[1]), "r"(a[2]), "r"(a[3]), "r"(b0), "r"(b1));
}
__device__ __forceinline__ float tanha(float x) {
    float r; asm("tanh.approx.f32 %0, %1;" : "=f"(r) : "f"(x)); return r;
}
__device__ __forceinline__ float sigm_(float x) {
    return fmaf(0.5f, tanha(0.5f * x), 0.5f);
}
__device__ __forceinline__ void split_bf16(float v, __nv_bfloat16& hi, __nv_bfloat16& lo) {
    hi = __float2bfloat16(v);
    lo = __float2bfloat16(v - __bfloat162float(hi));
}

extern __shared__ char smem[];

__global__ void __launch_bounds__(NTHREADS, 1)
lstm_wmma_kernel(const float* __restrict__ x,
                 const float* __restrict__ w_ih0, const float* __restrict__ w_hh0,
                 const float* __restrict__ b_ih0, const float* __restrict__ b_hh0,
                 const float* __restrict__ w_ih1, const float* __restrict__ w_hh1,
                 const float* __restrict__ b_ih1, const float* __restrict__ b_hh1,
                 const float* __restrict__ w_fc,  const float* __restrict__ b_fc,
                 float* __restrict__ out)
{
    const int tid  = threadIdx.x;
    const int w    = tid >> 5;          // warp 0..15 = m-tile
    const int lane = tid & 31;
    const int b0   = blockIdx.x * BT;

    uint32_t smb;
    asm("{ .reg .u64 t; cvta.to.shared.u64 t, %1; cvt.u32.u64 %0, t; }"
        : "=r"(smb) : "l"(smem));

    // ---- zero B operand buffers (h state starts 0; pads must be 0) ----
    for (int i = tid; i < (8 * B0S) / 4; i += NTHREADS) {
        ((uint32_t*)(smem + SM_B0H))[i] = 0;
        ((uint32_t*)(smem + SM_B0L))[i] = 0;
    }
    for (int i = tid; i < (8 * B1S) / 4; i += NTHREADS) {
        ((uint32_t*)(smem + SM_B1H))[i] = 0;
        ((uint32_t*)(smem + SM_B1L))[i] = 0;
    }

    // ---- stage weights as plain bf16 ----
    for (int i = tid; i < 256 * 64; i += NTHREADS) {
        int r = i >> 6, k = i & 63;
        *(__nv_bfloat16*)(smem + SM_W0H + r * W0S + k * 2) = __float2bfloat16(w_hh0[i]);
    }
    for (int i = tid; i < 256 * 128; i += NTHREADS) {
        int r = i >> 7, k = i & 127;
        float v = (k < 64) ? w_ih1[r * 64 + k] : w_hh1[r * 64 + (k - 64)];
        uint32_t off = (uint32_t)(k * 2) ^ (uint32_t)((r & 7) << 4);
        *(__nv_bfloat16*)(smem + SM_W1H + r * W1S + off) = __float2bfloat16(v);
    }

    float* g0f = (float*)(smem + SM_G0);
    float* g1f = (float*)(smem + SM_G1);
    float* xsf = (float*)(smem + SM_XS);
    float* h1f = (float*)(smem + SM_H1F);

    // x(t=0) -> xsf
    if (tid < 16) {
        int b = tid >> 1, qq = tid & 1;
        float4 v = *(const float4*)(x + (size_t)(b0 + b) * TSTEPS * IDIM + qq * 4);
        *(float4*)(xsf + b * 8 + qq * 4) = v;
    }

    // mma lane geometry (rows 16w .. 16w+15)
    const int mb    = 16 * w;
    const int aRow  = lane & 15;
    const int aHalf = lane >> 4;
    const int bn    = lane >> 2;
    const int bq    = lane & 3;
    const int dq    = lane & 3, dg = lane >> 2;

    // D-owner constants: batches gbA/gbB, rows rowA/rowB
    const int gbA = 2 * dq, gbB = gbA + 1;
    const int rowA = mb + dg, rowB = mb + dg + 8;
    const float bias0A = b_ih0[rowA] + b_hh0[rowA];
    const float bias0B = b_ih0[rowB] + b_hh0[rowB];
    const float bias1A = b_ih1[rowA] + b_hh1[rowA];
    const float bias1B = b_ih1[rowB] + b_hh1[rowB];
    float wxa[8], wxb[8];
    #pragma unroll
    for (int q = 0; q < 8; q++) {
        wxa[q] = w_ih0[rowA * IDIM + q];
        wxb[q] = w_ih0[rowB * IDIM + q];
    }

    // elem geometry
    const int eb = tid >> 6;     // batch 0..7
    const int eh = tid & 63;     // h index
    float c0 = 0.f, c1 = 0.f;

    __syncthreads();

    // ---- ALL A-frags (bf16 weights) register-resident for 512 steps ----
    uint32_t a0h[4][4];   // W0: 4 k-tiles
    uint32_t a1h[8][4];   // W1: 8 k-tiles
    #pragma unroll
    for (int kt = 0; kt < 4; kt++) {
        uint32_t ro = (uint32_t)(mb + aRow) * W0S + kt * 32 + aHalf * 16;
        ldmx4(a0h[kt], smb + SM_W0H + ro);
    }
    #pragma unroll
    for (int kt = 0; kt < 8; kt++) {
        int row = mb + aRow;
        uint32_t off = (uint32_t)(kt * 32 + aHalf * 16) ^ (uint32_t)((row & 7) << 4);
        ldmx4(a1h[kt], smb + SM_W1H + (uint32_t)row * W1S + off);
    }
    __syncthreads();

    for (int t = 0; t < TSTEPS; t++) {
        // ========== PHASE 1: GEMM0(t) + GEMM1(t-1), direct gate stores ==========
        {
            // xg(t) for this thread's 4 D-elements (x in xsf, exact fp32)
            float xA[8], xB[8];
            {
                float4 v0 = ((const float4*)xsf)[gbA * 2];
                float4 v1 = ((const float4*)xsf)[gbA * 2 + 1];
                xA[0]=v0.x; xA[1]=v0.y; xA[2]=v0.z; xA[3]=v0.w;
                xA[4]=v1.x; xA[5]=v1.y; xA[6]=v1.z; xA[7]=v1.w;
                float4 u0 = ((const float4*)xsf)[gbB * 2];
                float4 u1 = ((const float4*)xsf)[gbB * 2 + 1];
                xB[0]=u0.x; xB[1]=u0.y; xB[2]=u0.z; xB[3]=u0.w;
                xB[4]=u1.x; xB[5]=u1.y; xB[6]=u1.z; xB[7]=u1.w;
            }
            float xgAa = 0.f, xgBa = 0.f, xgAb = 0.f, xgBb = 0.f;
            #pragma unroll
            for (int q = 0; q < 8; q++) {
                xgAa = fmaf(xA[q], wxa[q], xgAa);
                xgBa = fmaf(xB[q], wxa[q], xgBa);
                xgAb = fmaf(xA[q], wxb[q], xgAb);
                xgBb = fmaf(xB[q], wxb[q], xgBb);
            }

            // GEMM0(t): W0 @ (h0hi + h0lo)
            float d0h[4] = {0,0,0,0}, d0l[4] = {0,0,0,0};
            #pragma unroll
            for (int kt = 0; kt < 4; kt++) {
                uint32_t boff = bn * B0S + kt * 32 + bq * 4;
                uint32_t bh0 = *(const uint32_t*)(smem + SM_B0H + boff);
                uint32_t bh1 = *(const uint32_t*)(smem + SM_B0H + boff + 16);
                uint32_t bl0 = *(const uint32_t*)(smem + SM_B0L + boff);
                uint32_t bl1 = *(const uint32_t*)(smem + SM_B0L + boff + 16);
                mma16816(d0h, a0h[kt], bh0, bh1);
                mma16816(d0l, a0h[kt], bl0, bl1);
            }
            g0f[gbA * GSTR + rowA] = d0h[0] + d0l[0] + xgAa + bias0A;
            g0f[gbB * GSTR + rowA] = d0h[1] + d0l[1] + xgBa + bias0A;
            g0f[gbA * GSTR + rowB] = d0h[2] + d0l[2] + xgAb + bias0B;
            g0f[gbB * GSTR + rowB] = d0h[3] + d0l[3] + xgBb + bias0B;

            // GEMM1(t-1): W1 @ [h0(t-1) | h1(t-2)]
            if (t > 0) {
                float d1h[4] = {0,0,0,0}, d1l[4] = {0,0,0,0};
                #pragma unroll
                for (int kt = 0; kt < 8; kt++) {
                    uint32_t boff = bn * B1S + kt * 32 + bq * 4;
                    uint32_t bh0 = *(const uint32_t*)(smem + SM_B1H + boff);
                    uint32_t bh1 = *(const uint32_t*)(smem + SM_B1H + boff + 16);
                    uint32_t bl0 = *(const uint32_t*)(smem + SM_B1L + boff);
                    uint32_t bl1 = *(const uint32_t*)(smem + SM_B1L + boff + 16);
                    mma16816(d1h, a1h[kt], bh0, bh1);
                    mma16816(d1l, a1h[kt], bl0, bl1);
                }
                g1f[gbA * GSTR + rowA] = d1h[0] + d1l[0] + bias1A;
                g1f[gbB * GSTR + rowA] = d1h[1] + d1l[1] + bias1A;
                g1f[gbA * GSTR + rowB] = d1h[2] + d1l[2] + bias1B;
                g1f[gbB * GSTR + rowB] = d1h[3] + d1l[3] + bias1B;
            }
        }
        __syncthreads();

        // ========== PHASE 2: elem0(t) + elem1(t-1) + x prefetch ==========
        {
            // elem0(t): h0(t) -> B0 (next GEMM0) and B1 atom0 (GEMM1(t))
            const float* g = g0f + eb * GSTR;
            float iv = sigm_(g[eh]);
            float fv = sigm_(g[eh + 64]);
            float gv = tanha(g[eh + 128]);
            float ov = sigm_(g[eh + 192]);
            c0 = fv * c0 + iv * gv;
            float hv = ov * tanha(c0);
            __nv_bfloat16 hi, lo; split_bf16(hv, hi, lo);
            *(__nv_bfloat16*)(smem + SM_B0H + eb * B0S + eh * 2) = hi;
            *(__nv_bfloat16*)(smem + SM_B0L + eb * B0S + eh * 2) = lo;
            *(__nv_bfloat16*)(smem + SM_B1H + eb * B1S + eh * 2) = hi;
            *(__nv_bfloat16*)(smem + SM_B1L + eb * B1S + eh * 2) = lo;

            // elem1(t-1): h1(t-1) -> B1 atom1
            if (t > 0) {
                const float* g1 = g1f + eb * GSTR;
                float iv1 = sigm_(g1[eh]);
                float fv1 = sigm_(g1[eh + 64]);
                float gv1 = tanha(g1[eh + 128]);
                float ov1 = sigm_(g1[eh + 192]);
                c1 = fv1 * c1 + iv1 * gv1;
                float hv1 = ov1 * tanha(c1);
                __nv_bfloat16 hi1, lo1; split_bf16(hv1, hi1, lo1);
                *(__nv_bfloat16*)(smem + SM_B1H + eb * B1S + 128 + eh * 2) = hi1;
                *(__nv_bfloat16*)(smem + SM_B1L + eb * B1S + 128 + eh * 2) = lo1;
            }

            // prefetch x(t+1)
            if (tid < 16 && t + 1 < TSTEPS) {
                int b = tid >> 1, qq = tid & 1;
                float4 v = *(const float4*)(x + (size_t)(b0 + b) * TSTEPS * IDIM
                                              + (size_t)(t + 1) * IDIM + qq * 4);
                *(float4*)(xsf + b * 8 + qq * 4) = v;
            }
        }
        __syncthreads();
    }

    // ========== EPILOGUE: GEMM1(T-1) + elem1(T-1) + FC ==========
    {
        float d1h[4] = {0,0,0,0}, d1l[4] = {0,0,0,0};
        #pragma unroll
        for (int kt = 0; kt < 8; kt++) {
            uint32_t boff = bn * B1S + kt * 32 + bq * 4;
            uint32_t bh0 = *(const uint32_t*)(smem + SM_B1H + boff);
            uint32_t bh1 = *(const uint32_t*)(smem + SM_B1H + boff + 16);
            uint32_t bl0 = *(const uint32_t*)(smem + SM_B1L + boff);
            uint32_t bl1 = *(const uint32_t*)(smem + SM_B1L + boff + 16);
            mma16816(d1h, a1h[kt], bh0, bh1);
            mma16816(d1l, a1h[kt], bl0, bl1);
        }
        g1f[gbA * GSTR + rowA] = d1h[0] + d1l[0] + bias1A;
        g1f[gbB * GSTR + rowA] = d1h[1] + d1l[1] + bias1A;
        g1f[gbA * GSTR + rowB] = d1h[2] + d1l[2] + bias1B;
        g1f[gbB * GSTR + rowB] = d1h[3] + d1l[3] + bias1B;
    }
    __syncthreads();
    {
        const float* g1 = g1f + eb * GSTR;
        float iv1 = sigm_(g1[eh]);
        float fv1 = sigm_(g1[eh + 64]);
        float gv1 = tanha(g1[eh + 128]);
        float ov1 = sigm_(g1[eh + 192]);
        c1 = fv1 * c1 + iv1 * gv1;
        h1f[eb * HID + eh] = ov1 * tanha(c1);
    }
    __syncthreads();

    if (tid < BT * ODIM) {
        int b = tid / ODIM, o = tid % ODIM;
        const float* hrow = h1f + b * HID;
        const float* wrow = w_fc + o * HID;
        float s = b_fc[o];
        #pragma unroll 16
        for (int k = 0; k < HID; k++) s = fmaf(hrow[k], wrow[k], s);
        out[(size_t)(b0 + b) * ODIM + o] = s;
    }
}

extern "C" void kernel_launch(void* const* d_in, const int* in_sizes, int n_in,
                              void* d_out, int out_size)
{
    (void)in_sizes; (void)n_in; (void)out_size;
    const float* x     = (const float*)d_in[0];
    const float* w_ih0 = (const float*)d_in[1];
    const float* w_hh0 = (const float*)d_in[2];
    const float* b_ih0 = (const float*)d_in[3];
    const float* b_hh0 = (const float*)d_in[4];
    const float* w_ih1 = (const float*)d_in[5];
    const float* w_hh1 = (const float*)d_in[6];
    const float* b_ih1 = (const float*)d_in[7];
    const float* b_hh1 = (const float*)d_in[8];
    const float* w_fc  = (const float*)d_in[9];
    const float* b_fc  = (const float*)d_in[10];

    cudaFuncSetAttribute(lstm_wmma_kernel,
                         cudaFuncAttributeMaxDynamicSharedMemorySize, SMEM_BYTES);
    lstm_wmma_kernel<<<NB, NTHREADS, SMEM_BYTES>>>(
        x, w_ih0, w_hh0, b_ih0, b_hh0, w_ih1, w_hh1, b_ih1, b_hh1, w_fc, b_fc,
        (float*)d_out);
}

// round 15
// speedup vs baseline: 1.1003x; 1.1003x over previous
#include <cuda_runtime.h>
#include <cuda_bf16.h>
#include <cstdint>
#include <cstddef>

// LSTM_824633721296: 2-layer LSTM (B=1024, T=512, I=8, H=64) + FC (O=10)
// Round-15 (resubmit of round-14; prior run died to an infra-level container
// failure, kernel is all-proven constructs): round-12 4-phase skeleton +
// direct gate stores (no RMW, no prestores), single h0 buffer (GEMM0 reads
// B1 atom0), x prefetch split LDG(phase A) -> STS(phase D).
// mma.sync m16n8k16, bf16 weights register-resident (zero ldmatrix in loop),
// h hi/lo 2-term. 512 threads, 1 m-tile/warp. tanh.approx activations.

#define BT       8
#define NB       128
#define NTHREADS 512
#define HID      64
#define TSTEPS   512
#define IDIM     8
#define ODIM     10

#define GSTR 260            // gate buffer stride (floats)
#define W0S  144            // W0 staging row stride bytes
#define W1S  256            // W1 staging row stride bytes (XOR-swizzled)
#define B1S  272            // B1 row stride bytes ([h0 | h1] bf16 + pad)

// smem byte offsets
#define SM_W0H 0            // [256][144] staging
#define SM_W1H 36864        // [256][256] swizzled
#define SM_B1H 102400       // [8][272]  [h0 | h1] hi
#define SM_B1L 104576       // [8][272]  lo
#define SM_G0  106752       // f32 [8][260]
#define SM_G1  115072       // f32 [8][260]
#define SM_XS  123392       // f32 [8][8]
#define SM_H1F 123648       // f32 [8][64]
#define SMEM_BYTES 125696

__device__ __forceinline__ void ldmx4(uint32_t r[4], uint32_t addr) {
    asm volatile("ldmatrix.sync.aligned.m8n8.x4.shared.b16 {%0,%1,%2,%3}, [%4];"
                 : "=r"(r[0]), "=r"(r[1]), "=r"(r[2]), "=r"(r[3]) : "r"(addr));
}
__device__ __forceinline__ void mma16816(float d[4], const uint32_t a[4],
                                         uint32_t b0, uint32_t b1) {
    asm volatile("mma.sync.aligned.m16n8k16.row.col.f32.bf16.bf16.f32 "
                 "{%0,%1,%2,%3}, {%4,%5,%6,%7}, {%8,%9}, {%0,%1,%2,%3};"
                 : "+f"(d[0]), "+f"(d[1]), "+f"(d[2]), "+f"(d[3])
                 : "r"(a[0]), "r"(a[1]), "r"(a[2]), "r"(a[3]), "r"(b0), "r"(b1));
}
__device__ __forceinline__ float tanha(float x) {
    float r; asm("tanh.approx.f32 %0, %1;" : "=f"(r) : "f"(x)); return r;
}
__device__ __forceinline__ float sigm_(float x) {
    return fmaf(0.5f, tanha(0.5f * x), 0.5f);
}
__device__ __forceinline__ void split_bf16(float v, __nv_bfloat16& hi, __nv_bfloat16& lo) {
    hi = __float2bfloat16(v);
    lo = __float2bfloat16(v - __bfloat162float(hi));
}

extern __shared__ char smem[];

__global__ void __launch_bounds__(NTHREADS, 1)
lstm_wmma_kernel(const float* __restrict__ x,
                 const float* __restrict__ w_ih0, const float* __restrict__ w_hh0,
                 const float* __restrict__ b_ih0, const float* __restrict__ b_hh0,
                 const float* __restrict__ w_ih1, const float* __restrict__ w_hh1,
                 const float* __restrict__ b_ih1, const float* __restrict__ b_hh1,
                 const float* __restrict__ w_fc,  const float* __restrict__ b_fc,
                 float* __restrict__ out)
{
    const int tid  = threadIdx.x;
    const int w    = tid >> 5;          // warp 0..15 = m-tile
    const int lane = tid & 31;
    const int b0   = blockIdx.x * BT;

    uint32_t smb;
    asm("{ .reg .u64 t; cvta.to.shared.u64 t, %1; cvt.u32.u64 %0, t; }"
        : "=r"(smb) : "l"(smem));

    // ---- zero B1 buffers (h state starts 0; pads must be 0) ----
    for (int i = tid; i < (8 * B1S) / 4; i += NTHREADS) {
        ((uint32_t*)(smem + SM_B1H))[i] = 0;
        ((uint32_t*)(smem + SM_B1L))[i] = 0;
    }

    // ---- stage weights as plain bf16 ----
    for (int i = tid; i < 256 * 64; i += NTHREADS) {
        int r = i >> 6, k = i & 63;
        *(__nv_bfloat16*)(smem + SM_W0H + r * W0S + k * 2) = __float2bfloat16(w_hh0[i]);
    }
    for (int i = tid; i < 256 * 128; i += NTHREADS) {
        int r = i >> 7, k = i & 127;
        float v = (k < 64) ? w_ih1[r * 64 + k] : w_hh1[r * 64 + (k - 64)];
        uint32_t off = (uint32_t)(k * 2) ^ (uint32_t)((r & 7) << 4);
        *(__nv_bfloat16*)(smem + SM_W1H + r * W1S + off) = __float2bfloat16(v);
    }

    float* g0f = (float*)(smem + SM_G0);
    float* g1f = (float*)(smem + SM_G1);
    float* xsf = (float*)(smem + SM_XS);
    float* h1f = (float*)(smem + SM_H1F);

    // x(t=0) -> xsf
    if (tid < 16) {
        int b = tid >> 1, qq = tid & 1;
        float4 v = *(const float4*)(x + (size_t)(b0 + b) * TSTEPS * IDIM + qq * 4);
        *(float4*)(xsf + b * 8 + qq * 4) = v;
    }

    // mma lane geometry (rows 16w .. 16w+15)
    const int mb    = 16 * w;
    const int aRow  = lane & 15;
    const int aHalf = lane >> 4;
    const int bn    = lane >> 2;
    const int bq    = lane & 3;
    const int dq    = lane & 3, dg = lane >> 2;

    // D-owner constants: batches gbA/gbB, rows rowA/rowB
    const int gbA = 2 * dq, gbB = gbA + 1;
    const int rowA = mb + dg, rowB = mb + dg + 8;
    const float bias0A = b_ih0[rowA] + b_hh0[rowA];
    const float bias0B = b_ih0[rowB] + b_hh0[rowB];
    const float bias1A = b_ih1[rowA] + b_hh1[rowA];
    const float bias1B = b_ih1[rowB] + b_hh1[rowB];
    float wxa[8], wxb[8];
    #pragma unroll
    for (int q = 0; q < 8; q++) {
        wxa[q] = w_ih0[rowA * IDIM + q];
        wxb[q] = w_ih0[rowB * IDIM + q];
    }

    // elem geometry
    const int eb = tid >> 6;     // batch 0..7
    const int eh = tid & 63;     // h index
    float c0 = 0.f, c1 = 0.f;

    __syncthreads();

    // ---- ALL A-frags (bf16 weights) register-resident for 512 steps ----
    uint32_t a0h[4][4];   // W0: 4 k-tiles
    uint32_t a1h[8][4];   // W1: 8 k-tiles
    #pragma unroll
    for (int kt = 0; kt < 4; kt++) {
        uint32_t ro = (uint32_t)(mb + aRow) * W0S + kt * 32 + aHalf * 16;
        ldmx4(a0h[kt], smb + SM_W0H + ro);
    }
    #pragma unroll
    for (int kt = 0; kt < 8; kt++) {
        int row = mb + aRow;
        uint32_t off = (uint32_t)(kt * 32 + aHalf * 16) ^ (uint32_t)((row & 7) << 4);
        ldmx4(a1h[kt], smb + SM_W1H + (uint32_t)row * W1S + off);
    }
    __syncthreads();

    for (int t = 0; t < TSTEPS; t++) {
        // ========== PHASE A: GEMM0(t) -> g0f (direct store, xg+bias folded) ==========
        // issue x(t+1) global load NOW; consumed (STS) in phase D
        float4 xpre = make_float4(0.f, 0.f, 0.f, 0.f);
        const bool doPre = (tid < 16) && (t + 1 < TSTEPS);
        if (doPre) {
            int b = tid >> 1, qq = tid & 1;
            xpre = *(const float4*)(x + (size_t)(b0 + b) * TSTEPS * IDIM
                                      + (size_t)(t + 1) * IDIM + qq * 4);
        }
        {
            // xg(t): exact fp32 for this thread's 4 D-elements
            float4 vA0 = ((const float4*)xsf)[gbA * 2];
            float4 vA1 = ((const float4*)xsf)[gbA * 2 + 1];
            float4 vB0 = ((const float4*)xsf)[gbB * 2];
            float4 vB1 = ((const float4*)xsf)[gbB * 2 + 1];
            float xA[8] = {vA0.x, vA0.y, vA0.z, vA0.w, vA1.x, vA1.y, vA1.z, vA1.w};
            float xB[8] = {vB0.x, vB0.y, vB0.z, vB0.w, vB1.x, vB1.y, vB1.z, vB1.w};
            float xgAa = 0.f, xgBa = 0.f, xgAb = 0.f, xgBb = 0.f;
            #pragma unroll
            for (int q = 0; q < 8; q++) {
                xgAa = fmaf(xA[q], wxa[q], xgAa);
                xgBa = fmaf(xB[q], wxa[q], xgBa);
                xgAb = fmaf(xA[q], wxb[q], xgAb);
                xgBb = fmaf(xB[q], wxb[q], xgBb);
            }

            float d0h[4] = {0,0,0,0}, d0l[4] = {0,0,0,0};
            #pragma unroll
            for (int kt = 0; kt < 4; kt++) {          // B1 atom0 = h0 (first 128B of row)
                uint32_t boff = bn * B1S + kt * 32 + bq * 4;
                uint32_t bh0 = *(const uint32_t*)(smem + SM_B1H + boff);
                uint32_t bh1 = *(const uint32_t*)(smem + SM_B1H + boff + 16);
                uint32_t bl0 = *(const uint32_t*)(smem + SM_B1L + boff);
                uint32_t bl1 = *(const uint32_t*)(smem + SM_B1L + boff + 16);
                mma16816(d0h, a0h[kt], bh0, bh1);
                mma16816(d0l, a0h[kt], bl0, bl1);
            }
            g0f[gbA * GSTR + rowA] = d0h[0] + d0l[0] + xgAa + bias0A;
            g0f[gbB * GSTR + rowA] = d0h[1] + d0l[1] + xgBa + bias0A;
            g0f[gbA * GSTR + rowB] = d0h[2] + d0l[2] + xgAb + bias0B;
            g0f[gbB * GSTR + rowB] = d0h[3] + d0l[3] + xgBb + bias0B;
        }
        __syncthreads();

        // ========== PHASE B: elem0(t) -> h0(t) into B1 atom0 ==========
        {
            const float* g = g0f + eb * GSTR;
            float iv = sigm_(g[eh]);
            float fv = sigm_(g[eh + 64]);
            float gv = tanha(g[eh + 128]);
            float ov = sigm_(g[eh + 192]);
            c0 = fv * c0 + iv * gv;
            float hv = ov * tanha(c0);
            __nv_bfloat16 hi, lo; split_bf16(hv, hi, lo);
            *(__nv_bfloat16*)(smem + SM_B1H + eb * B1S + eh * 2) = hi;
            *(__nv_bfloat16*)(smem + SM_B1L + eb * B1S + eh * 2) = lo;
        }
        __syncthreads();

        // ========== PHASE C: GEMM1(t) -> g1f (direct store, bias folded) ==========
        {
            float d1h[4] = {0,0,0,0}, d1l[4] = {0,0,0,0};
            #pragma unroll
            for (int kt = 0; kt < 8; kt++) {          // full row: [h0(t) | h1(t-1)]
                uint32_t boff = bn * B1S + kt * 32 + bq * 4;
                uint32_t bh0 = *(const uint32_t*)(smem + SM_B1H + boff);
                uint32_t bh1 = *(const uint32_t*)(smem + SM_B1H + boff + 16);
                uint32_t bl0 = *(const uint32_t*)(smem + SM_B1L + boff);
                uint32_t bl1 = *(const uint32_t*)(smem + SM_B1L + boff + 16);
                mma16816(d1h, a1h[kt], bh0, bh1);
                mma16816(d1l, a1h[kt], bl0, bl1);
            }
            g1f[gbA * GSTR + rowA] = d1h[0] + d1l[0] + bias1A;
            g1f[gbB * GSTR + rowA] = d1h[1] + d1l[1] + bias1A;
            g1f[gbA * GSTR + rowB] = d1h[2] + d1l[2] + bias1B;
            g1f[gbB * GSTR + rowB] = d1h[3] + d1l[3] + bias1B;
        }
        __syncthreads();

        // ========== PHASE D: elem1(t) -> h1(t) into B1 atom1; store x(t+1) ==========
        {
            const float* g = g1f + eb * GSTR;
            float iv = sigm_(g[eh]);
            float fv = sigm_(g[eh + 64]);
            float gv = tanha(g[eh + 128]);
            float ov = sigm_(g[eh + 192]);
            c1 = fv * c1 + iv * gv;
            float hv = ov * tanha(c1);
            __nv_bfloat16 hi, lo; split_bf16(hv, hi, lo);
            *(__nv_bfloat16*)(smem + SM_B1H + eb * B1S + 128 + eh * 2) = hi;
            *(__nv_bfloat16*)(smem + SM_B1L + eb * B1S + 128 + eh * 2) = lo;
            if (t == TSTEPS - 1) h1f[eb * HID + eh] = hv;
        }
        if (doPre) {
            int b = tid >> 1, qq = tid & 1;
            *(float4*)(xsf + b * 8 + qq * 4) = xpre;
        }
        __syncthreads();
    }

    // ================= FC: out = h1_final @ w_fc^T + b_fc =================
    if (tid < BT * ODIM) {
        int b = tid / ODIM, o = tid % ODIM;
        const float* hrow = h1f + b * HID;
        const float* wrow = w_fc + o * HID;
        float s = b_fc[o];
        #pragma unroll 16
        for (int k = 0; k < HID; k++) s = fmaf(hrow[k], wrow[k], s);
        out[(size_t)(b0 + b) * ODIM + o] = s;
    }
}

extern "C" void kernel_launch(void* const* d_in, const int* in_sizes, int n_in,
                              void* d_out, int out_size)
{
    (void)in_sizes; (void)n_in; (void)out_size;
    const float* x     = (const float*)d_in[0];
    const float* w_ih0 = (const float*)d_in[1];
    const float* w_hh0 = (const float*)d_in[2];
    const float* b_ih0 = (const float*)d_in[3];
    const float* b_hh0 = (const float*)d_in[4];
    const float* w_ih1 = (const float*)d_in[5];
    const float* w_hh1 = (const float*)d_in[6];
    const float* b_ih1 = (const float*)d_in[7];
    const float* b_hh1 = (const float*)d_in[8];
    const float* w_fc  = (const float*)d_in[9];
    const float* b_fc  = (const float*)d_in[10];

    cudaFuncSetAttribute(lstm_wmma_kernel,
                         cudaFuncAttributeMaxDynamicSharedMemorySize, SMEM_BYTES);
    lstm_wmma_kernel<<<NB, NTHREADS, SMEM_BYTES>>>(
        x, w_ih0, w_hh0, b_ih0, b_hh0, w_ih1, w_hh1, b_ih1, b_hh1, w_fc, b_fc,
        (float*)d_out);
}

// round 16
// speedup vs baseline: 1.3183x; 1.1982x over previous
#include <cuda_runtime.h>
#include <cuda_bf16.h>
#include <cstdint>
#include <cstddef>

// LSTM_824633721296: 2-layer LSTM (B=1024, T=512, I=8, H=64) + FC (O=10)
// Round-16: merged 2-phase pipeline (2 syncthreads/step).
//   Phase1 = GEMM0(t) + GEMM1(t-1): 4 independent mma chains, direct gate
//            stores (xg+bias folded). x(t+1) LDG issued here.
//   Phase2 = elem0(t) + elem1(t-1): 2 independent MUFU chains. x STS here.
// Single B1 buffer [h0|h1] hi/lo; bf16 weights register-resident (zero
// ldmatrix in loop). 512 threads, 1 m-tile/warp. tanh.approx activations.

#define BT       8
#define NB       128
#define NTHREADS 512
#define HID      64
#define TSTEPS   512
#define IDIM     8
#define ODIM     10

#define GSTR 260            // gate buffer stride (floats)
#define W0S  144            // W0 staging row stride bytes
#define W1S  256            // W1 staging row stride bytes (XOR-swizzled)
#define B1S  272            // B1 row stride bytes ([h0 | h1] bf16 + pad)

// smem byte offsets
#define SM_W0H 0            // [256][144] staging
#define SM_W1H 36864        // [256][256] swizzled
#define SM_B1H 102400       // [8][272]  [h0 | h1] hi
#define SM_B1L 104576       // [8][272]  lo
#define SM_G0  106752       // f32 [8][260]
#define SM_G1  115072       // f32 [8][260]
#define SM_XS  123392       // f32 [8][8]
#define SM_H1F 123648       // f32 [8][64]
#define SMEM_BYTES 125696

__device__ __forceinline__ void ldmx4(uint32_t r[4], uint32_t addr) {
    asm volatile("ldmatrix.sync.aligned.m8n8.x4.shared.b16 {%0,%1,%2,%3}, [%4];"
                 : "=r"(r[0]), "=r"(r[1]), "=r"(r[2]), "=r"(r[3]) : "r"(addr));
}
__device__ __forceinline__ void mma16816(float d[4], const uint32_t a[4],
                                         uint32_t b0, uint32_t b1) {
    asm volatile("mma.sync.aligned.m16n8k16.row.col.f32.bf16.bf16.f32 "
                 "{%0,%1,%2,%3}, {%4,%5,%6,%7}, {%8,%9}, {%0,%1,%2,%3};"
                 : "+f"(d[0]), "+f"(d[1]), "+f"(d[2]), "+f"(d[3])
                 : "r"(a[0]), "r"(a[1]), "r"(a[2]), "r"(a[3]), "r"(b0), "r"(b1));
}
__device__ __forceinline__ float tanha(float x) {
    float r; asm("tanh.approx.f32 %0, %1;" : "=f"(r) : "f"(x)); return r;
}
__device__ __forceinline__ float sigm_(float x) {
    return fmaf(0.5f, tanha(0.5f * x), 0.5f);
}
__device__ __forceinline__ void split_bf16(float v, __nv_bfloat16& hi, __nv_bfloat16& lo) {
    hi = __float2bfloat16(v);
    lo = __float2bfloat16(v - __bfloat162float(hi));
}

extern __shared__ char smem[];

__global__ void __launch_bounds__(NTHREADS, 1)
lstm_wmma_kernel(const float* __restrict__ x,
                 const float* __restrict__ w_ih0, const float* __restrict__ w_hh0,
                 const float* __restrict__ b_ih0, const float* __restrict__ b_hh0,
                 const float* __restrict__ w_ih1, const float* __restrict__ w_hh1,
                 const float* __restrict__ b_ih1, const float* __restrict__ b_hh1,
                 const float* __restrict__ w_fc,  const float* __restrict__ b_fc,
                 float* __restrict__ out)
{
    const int tid  = threadIdx.x;
    const int w    = tid >> 5;          // warp 0..15 = m-tile
    const int lane = tid & 31;
    const int b0   = blockIdx.x * BT;

    uint32_t smb;
    asm("{ .reg .u64 t; cvta.to.shared.u64 t, %1; cvt.u32.u64 %0, t; }"
        : "=r"(smb) : "l"(smem));

    // ---- zero B1 buffers (h state starts 0; pads must be 0) ----
    for (int i = tid; i < (8 * B1S) / 4; i += NTHREADS) {
        ((uint32_t*)(smem + SM_B1H))[i] = 0;
        ((uint32_t*)(smem + SM_B1L))[i] = 0;
    }

    // ---- stage weights as plain bf16 ----
    for (int i = tid; i < 256 * 64; i += NTHREADS) {
        int r = i >> 6, k = i & 63;
        *(__nv_bfloat16*)(smem + SM_W0H + r * W0S + k * 2) = __float2bfloat16(w_hh0[i]);
    }
    for (int i = tid; i < 256 * 128; i += NTHREADS) {
        int r = i >> 7, k = i & 127;
        float v = (k < 64) ? w_ih1[r * 64 + k] : w_hh1[r * 64 + (k - 64)];
        uint32_t off = (uint32_t)(k * 2) ^ (uint32_t)((r & 7) << 4);
        *(__nv_bfloat16*)(smem + SM_W1H + r * W1S + off) = __float2bfloat16(v);
    }

    float* g0f = (float*)(smem + SM_G0);
    float* g1f = (float*)(smem + SM_G1);
    float* xsf = (float*)(smem + SM_XS);
    float* h1f = (float*)(smem + SM_H1F);

    // x(t=0) -> xsf
    if (tid < 16) {
        int b = tid >> 1, qq = tid & 1;
        float4 v = *(const float4*)(x + (size_t)(b0 + b) * TSTEPS * IDIM + qq * 4);
        *(float4*)(xsf + b * 8 + qq * 4) = v;
    }

    // mma lane geometry (rows 16w .. 16w+15)
    const int mb    = 16 * w;
    const int aRow  = lane & 15;
    const int aHalf = lane >> 4;
    const int bn    = lane >> 2;
    const int bq    = lane & 3;
    const int dq    = lane & 3, dg = lane >> 2;

    // D-owner constants
    const int gbA = 2 * dq, gbB = gbA + 1;
    const int rowA = mb + dg, rowB = mb + dg + 8;
    const float bias0A = b_ih0[rowA] + b_hh0[rowA];
    const float bias0B = b_ih0[rowB] + b_hh0[rowB];
    const float bias1A = b_ih1[rowA] + b_hh1[rowA];
    const float bias1B = b_ih1[rowB] + b_hh1[rowB];
    float wxa[8], wxb[8];
    #pragma unroll
    for (int q = 0; q < 8; q++) {
        wxa[q] = w_ih0[rowA * IDIM + q];
        wxb[q] = w_ih0[rowB * IDIM + q];
    }

    // elem geometry
    const int eb = tid >> 6;     // batch 0..7
    const int eh = tid & 63;     // h index
    float c0 = 0.f, c1 = 0.f;

    __syncthreads();

    // ---- ALL A-frags (bf16 weights) register-resident for 512 steps ----
    uint32_t a0h[4][4];   // W0: 4 k-tiles
    uint32_t a1h[8][4];   // W1: 8 k-tiles
    #pragma unroll
    for (int kt = 0; kt < 4; kt++) {
        uint32_t ro = (uint32_t)(mb + aRow) * W0S + kt * 32 + aHalf * 16;
        ldmx4(a0h[kt], smb + SM_W0H + ro);
    }
    #pragma unroll
    for (int kt = 0; kt < 8; kt++) {
        int row = mb + aRow;
        uint32_t off = (uint32_t)(kt * 32 + aHalf * 16) ^ (uint32_t)((row & 7) << 4);
        ldmx4(a1h[kt], smb + SM_W1H + (uint32_t)row * W1S + off);
    }
    __syncthreads();

    for (int t = 0; t < TSTEPS; t++) {
        // ===== PHASE 1: GEMM0(t) + GEMM1(t-1), direct stores; x(t+1) LDG =====
        float4 xpre = make_float4(0.f, 0.f, 0.f, 0.f);
        const bool doPre = (tid < 16) && (t + 1 < TSTEPS);
        if (doPre) {
            int b = tid >> 1, qq = tid & 1;
            xpre = *(const float4*)(x + (size_t)(b0 + b) * TSTEPS * IDIM
                                      + (size_t)(t + 1) * IDIM + qq * 4);
        }
        {
            // xg(t): exact fp32
            float4 vA0 = ((const float4*)xsf)[gbA * 2];
            float4 vA1 = ((const float4*)xsf)[gbA * 2 + 1];
            float4 vB0 = ((const float4*)xsf)[gbB * 2];
            float4 vB1 = ((const float4*)xsf)[gbB * 2 + 1];
            float xA[8] = {vA0.x, vA0.y, vA0.z, vA0.w, vA1.x, vA1.y, vA1.z, vA1.w};
            float xB[8] = {vB0.x, vB0.y, vB0.z, vB0.w, vB1.x, vB1.y, vB1.z, vB1.w};
            float xgAa = 0.f, xgBa = 0.f, xgAb = 0.f, xgBb = 0.f;
            #pragma unroll
            for (int q = 0; q < 8; q++) {
                xgAa = fmaf(xA[q], wxa[q], xgAa);
                xgBa = fmaf(xB[q], wxa[q], xgBa);
                xgAb = fmaf(xA[q], wxb[q], xgAb);
                xgBb = fmaf(xB[q], wxb[q], xgBb);
            }

            // GEMM0(t): W0 @ h0(t-1)  (B1 atom0)
            float d0h[4] = {0,0,0,0}, d0l[4] = {0,0,0,0};
            // GEMM1(t-1): W1 @ [h0(t-1) | h1(t-2)] (full B1 row)
            float d1h[4] = {0,0,0,0}, d1l[4] = {0,0,0,0};

            #pragma unroll
            for (int kt = 0; kt < 8; kt++) {
                uint32_t boff = bn * B1S + kt * 32 + bq * 4;
                uint32_t bh0 = *(const uint32_t*)(smem + SM_B1H + boff);
                uint32_t bh1 = *(const uint32_t*)(smem + SM_B1H + boff + 16);
                uint32_t bl0 = *(const uint32_t*)(smem + SM_B1L + boff);
                uint32_t bl1 = *(const uint32_t*)(smem + SM_B1L + boff + 16);
                if (kt < 4) {                          // shared with GEMM0
                    mma16816(d0h, a0h[kt], bh0, bh1);
                    mma16816(d0l, a0h[kt], bl0, bl1);
                }
                if (t > 0) {
                    mma16816(d1h, a1h[kt], bh0, bh1);
                    mma16816(d1l, a1h[kt], bl0, bl1);
                }
            }
            g0f[gbA * GSTR + rowA] = d0h[0] + d0l[0] + xgAa + bias0A;
            g0f[gbB * GSTR + rowA] = d0h[1] + d0l[1] + xgBa + bias0A;
            g0f[gbA * GSTR + rowB] = d0h[2] + d0l[2] + xgAb + bias0B;
            g0f[gbB * GSTR + rowB] = d0h[3] + d0l[3] + xgBb + bias0B;
            if (t > 0) {
                g1f[gbA * GSTR + rowA] = d1h[0] + d1l[0] + bias1A;
                g1f[gbB * GSTR + rowA] = d1h[1] + d1l[1] + bias1A;
                g1f[gbA * GSTR + rowB] = d1h[2] + d1l[2] + bias1B;
                g1f[gbB * GSTR + rowB] = d1h[3] + d1l[3] + bias1B;
            }
        }
        __syncthreads();

        // ===== PHASE 2: elem0(t) + elem1(t-1); x(t+1) STS =====
        {
            // elem0(t): h0(t) -> B1 atom0
            const float* g = g0f + eb * GSTR;
            float iv = sigm_(g[eh]);
            float fv = sigm_(g[eh + 64]);
            float gv = tanha(g[eh + 128]);
            float ov = sigm_(g[eh + 192]);
            c0 = fv * c0 + iv * gv;
            float hv = ov * tanha(c0);
            __nv_bfloat16 hi, lo; split_bf16(hv, hi, lo);
            *(__nv_bfloat16*)(smem + SM_B1H + eb * B1S + eh * 2) = hi;
            *(__nv_bfloat16*)(smem + SM_B1L + eb * B1S + eh * 2) = lo;

            // elem1(t-1): h1(t-1) -> B1 atom1 (independent MUFU chain)
            if (t > 0) {
                const float* g1 = g1f + eb * GSTR;
                float iv1 = sigm_(g1[eh]);
                float fv1 = sigm_(g1[eh + 64]);
                float gv1 = tanha(g1[eh + 128]);
                float ov1 = sigm_(g1[eh + 192]);
                c1 = fv1 * c1 + iv1 * gv1;
                float hv1 = ov1 * tanha(c1);
                __nv_bfloat16 hi1, lo1; split_bf16(hv1, hi1, lo1);
                *(__nv_bfloat16*)(smem + SM_B1H + eb * B1S + 128 + eh * 2) = hi1;
                *(__nv_bfloat16*)(smem + SM_B1L + eb * B1S + 128 + eh * 2) = lo1;
            }
        }
        if (doPre) {
            int b = tid >> 1, qq = tid & 1;
            *(float4*)(xsf + b * 8 + qq * 4) = xpre;
        }
        __syncthreads();
    }

    // ===== EPILOGUE: GEMM1(T-1) + elem1(T-1) + FC =====
    {
        float d1h[4] = {0,0,0,0}, d1l[4] = {0,0,0,0};
        #pragma unroll
        for (int kt = 0; kt < 8; kt++) {
            uint32_t boff = bn * B1S + kt * 32 + bq * 4;
            uint32_t bh0 = *(const uint32_t*)(smem + SM_B1H + boff);
            uint32_t bh1 = *(const uint32_t*)(smem + SM_B1H + boff + 16);
            uint32_t bl0 = *(const uint32_t*)(smem + SM_B1L + boff);
            uint32_t bl1 = *(const uint32_t*)(smem + SM_B1L + boff + 16);
            mma16816(d1h, a1h[kt], bh0, bh1);
            mma16816(d1l, a1h[kt], bl0, bl1);
        }
        g1f[gbA * GSTR + rowA] = d1h[0] + d1l[0] + bias1A;
        g1f[gbB * GSTR + rowA] = d1h[1] + d1l[1] + bias1A;
        g1f[gbA * GSTR + rowB] = d1h[2] + d1l[2] + bias1B;
        g1f[gbB * GSTR + rowB] = d1h[3] + d1l[3] + bias1B;
    }
    __syncthreads();
    {
        const float* g1 = g1f + eb * GSTR;
        float iv1 = sigm_(g1[eh]);
        float fv1 = sigm_(g1[eh + 64]);
        float gv1 = tanha(g1[eh + 128]);
        float ov1 = sigm_(g1[eh + 192]);
        c1 = fv1 * c1 + iv1 * gv1;
        h1f[eb * HID + eh] = ov1 * tanha(c1);
    }
    __syncthreads();

    if (tid < BT * ODIM) {
        int b = tid / ODIM, o = tid % ODIM;
        const float* hrow = h1f + b * HID;
        const float* wrow = w_fc + o * HID;
        float s = b_fc[o];
        #pragma unroll 16
        for (int k = 0; k < HID; k++) s = fmaf(hrow[k], wrow[k], s);
        out[(size_t)(b0 + b) * ODIM + o] = s;
    }
}

extern "C" void kernel_launch(void* const* d_in, const int* in_sizes, int n_in,
                              void* d_out, int out_size)
{
    (void)in_sizes; (void)n_in; (void)out_size;
    const float* x     = (const float*)d_in[0];
    const float* w_ih0 = (const float*)d_in[1];
    const float* w_hh0 = (const float*)d_in[2];
    const float* b_ih0 = (const float*)d_in[3];
    const float* b_hh0 = (const float*)d_in[4];
    const float* w_ih1 = (const float*)d_in[5];
    const float* w_hh1 = (const float*)d_in[6];
    const float* b_ih1 = (const float*)d_in[7];
    const float* b_hh1 = (const float*)d_in[8];
    const float* w_fc  = (const float*)d_in[9];
    const float* b_fc  = (const float*)d_in[10];

    cudaFuncSetAttribute(lstm_wmma_kernel,
                         cudaFuncAttributeMaxDynamicSharedMemorySize, SMEM_BYTES);
    lstm_wmma_kernel<<<NB, NTHREADS, SMEM_BYTES>>>(
        x, w_ih0, w_hh0, b_ih0, b_hh0, w_ih1, w_hh1, b_ih1, b_hh1, w_fc, b_fc,
        (float*)d_out);
}